// round 1
// baseline (speedup 1.0000x reference)
#include <cuda_runtime.h>
#include <cstddef>

// PCEN: out = (x / (FLOOR + ema(x))^alpha + delta)^(1/root) - delta^(1/root)
// ema: m_t = s*x_t + (1-s)*m_{t-1}, m_0 = x_0, s = 0.025.
//
// Strategy: EMA decays as 0.975^k, so split T into chunks with a 449-row halo
// (error < 1.3e-5 abs, far under the 1e-3 threshold). This turns 8192 sequential
// recurrences into 32768 parallel ones (1024 warps) at 1.33x read amplification.

namespace {
constexpr int   Bn = 64, Tn = 4096, Cn = 128;
constexpr float S_COEF = 0.025f;
constexpr float OMS    = 1.0f - 0.025f;   // 0.975
constexpr float FLOORV = 1e-6f;
constexpr int   NC     = 4;               // chunks along T
constexpr int   CHUNK  = Tn / NC;         // 1024
constexpr int   HALO   = 449;             // 0.975^449 ~ 1.2e-5
constexpr int   U      = 16;              // prefetch depth (rows per tile)
constexpr int   THREADS = 256;            // 8 warps/block
constexpr int   NWARPS  = Bn * NC * (Cn / 32);  // 1024
constexpr int   NBLOCKS = NWARPS * 32 / THREADS; // 128
}

__device__ __forceinline__ float f_lg2(float x) {
    float r; asm("lg2.approx.f32 %0, %1;" : "=f"(r) : "f"(x)); return r;
}
__device__ __forceinline__ float f_ex2(float x) {
    float r; asm("ex2.approx.f32 %0, %1;" : "=f"(r) : "f"(x)); return r;
}
__device__ __forceinline__ float f_sqt(float x) {
    float r; asm("sqrt.approx.f32 %0, %1;" : "=f"(r) : "f"(x)); return r;
}

// Pointwise PCEN given smoothed value m and raw x. SQ = (1/root == 0.5) fast path.
template <bool SQ>
__device__ __forceinline__ float pcen_pt(float xv, float m, float na, float d,
                                         float ri, float t3) {
    float inv_t1 = f_ex2(na * f_lg2(m + FLOORV));   // (FLOOR+m)^(-alpha)
    float y      = fmaf(xv, inv_t1, d);             // x/term1 + delta
    float t2     = SQ ? f_sqt(y) : f_ex2(ri * f_lg2(y));
    return t2 - t3;
}

template <bool SQ>
__device__ __forceinline__ void run_seq(const float* __restrict__ px,
                                        float* __restrict__ po,
                                        int tstart, int t0, int tend,
                                        float na, float d, float ri, float t3) {
    // px -> x[b, tstart, c];  po -> out[b, t0, c]
    float m = px[0];                    // m_{tstart} = x_{tstart} (exact for t=0,
    const float* p = px + Cn;           //              approx init inside halo)
    if (tstart == t0) {                 // chunk 0: row 0 emitted with m = x_0
        po[0] = pcen_pt<SQ>(m, m, na, d, ri, t3);
        po += Cn;
    }

    // ---- halo burn-in: rows (tstart, t0) — EMA update only ----
    int nh = t0 - (tstart + 1);         // 448 for chunks > 0, <0 for chunk 0
    #pragma unroll 8
    for (int i = 0; i < nh; ++i) {
        m = fmaf(OMS, m, S_COEF * p[0]);
        p += Cn;
    }

    // ---- emit region ----
    int ne = (tstart == t0) ? (tend - t0 - 1) : (tend - t0);
    int main_iters = ne / U;            // 64 (chunks>0) or 63 (chunk 0)
    int rem        = ne - main_iters * U;

    for (int it = 0; it < main_iters; ++it) {
        float xs[U], sx[U], os[U];
        #pragma unroll
        for (int i = 0; i < U; ++i) xs[i] = p[i * Cn];      // batched LDGs (MLP=16)
        #pragma unroll
        for (int i = 0; i < U; ++i) sx[i] = S_COEF * xs[i]; // off the m-chain
        #pragma unroll
        for (int i = 0; i < U; ++i) {
            m = fmaf(OMS, m, sx[i]);                        // 4-cyc dependent chain
            os[i] = pcen_pt<SQ>(xs[i], m, na, d, ri, t3);
        }
        #pragma unroll
        for (int i = 0; i < U; ++i) po[i * Cn] = os[i];
        p  += U * Cn;
        po += U * Cn;
    }
    for (int i = 0; i < rem; ++i) {
        float xv = p[i * Cn];
        m = fmaf(OMS, m, S_COEF * xv);
        po[i * Cn] = pcen_pt<SQ>(xv, m, na, d, ri, t3);
    }
}

__global__ void __launch_bounds__(THREADS, 1)
pcen_kernel(const float* __restrict__ x,
            const float* __restrict__ alpha,
            const float* __restrict__ delta,
            const float* __restrict__ root,
            float* __restrict__ out) {
    int gtid = blockIdx.x * blockDim.x + threadIdx.x;
    int w    = gtid >> 5;
    int lane = threadIdx.x & 31;

    // warp -> (b, chunk, channel-quarter); 16 warps per batch
    int b       = w >> 4;
    int r2      = w & 15;
    int chunk   = r2 >> 2;
    int quarter = r2 & 3;
    int c       = quarter * 32 + lane;

    // per-channel constants
    float a  = fminf(alpha[c], 1.0f);
    float d  = delta[c];
    float ri = 1.0f / fmaxf(root[c], 1.0f);
    float na = -a;
    bool  sq = (ri == 0.5f);
    // term3 computed with the SAME approx path as term2 so the x->0 limit
    // cancels exactly (out -> 0 like the reference).
    float t3 = sq ? f_sqt(d) : f_ex2(ri * f_lg2(d));

    int t0     = chunk * CHUNK;
    int tstart = t0 - HALO; if (tstart < 0) tstart = 0;
    int tend   = t0 + CHUNK;

    const float* px = x   + ((size_t)b * Tn + tstart) * Cn + c;
    float*       po = out + ((size_t)b * Tn + t0)     * Cn + c;

    if (sq) run_seq<true >(px, po, tstart, t0, tend, na, d, ri, t3);
    else    run_seq<false>(px, po, tstart, t0, tend, na, d, ri, t3);
}

extern "C" void kernel_launch(void* const* d_in, const int* in_sizes, int n_in,
                              void* d_out, int out_size) {
    const float* x     = (const float*)d_in[0];
    const float* alpha = (const float*)d_in[1];
    const float* delta = (const float*)d_in[2];
    const float* root  = (const float*)d_in[3];
    float*       out   = (float*)d_out;
    (void)in_sizes; (void)n_in; (void)out_size;

    pcen_kernel<<<NBLOCKS, THREADS>>>(x, alpha, delta, root, out);
}

// round 2
// speedup vs baseline: 1.3077x; 1.3077x over previous
#include <cuda_runtime.h>
#include <cstddef>

// PCEN: out = (x / (FLOOR + ema(x))^alpha + delta)^(1/root) - delta^(1/root)
// ema: m_t = s*x_t + (1-s)*m_{t-1}, m_0 = x_0, s = 0.025.
//
// R2: concurrency-limited fix. float2 per thread (2 channels), NC=8 chunks with
// 321-row halo (decay 0.975^320 ~ 3e-4), 256 blocks x 128 threads all-resident.
// Halo re-reads hit L2 (neighbor chunk's emit rows); output stores streamed
// (.cs) to keep the input resident in L2.

namespace {
constexpr int   Bn = 64, Tn = 4096, Cn = 128;
constexpr float S_COEF = 0.025f;
constexpr float INV_S  = 40.0f;           // 1/0.025
constexpr float OMS    = 0.975f;
constexpr float FLOORV = 1e-6f;
constexpr int   NC     = 8;               // chunks along T
constexpr int   CHUNK  = Tn / NC;         // 512
constexpr int   HALO   = 321;             // 320 burn-in updates -> 3e-4 decay
constexpr int   U      = 16;              // rows per tile (MLP)
constexpr int   THREADS = 128;            // 4 warps/block
constexpr int   NWARPS  = Bn * NC * 2;    // 1024 float2-warps
constexpr int   NBLOCKS = NWARPS * 32 / THREADS;  // 256
constexpr int   STRIDE  = Cn / 2;         // float2 elems per T-row
}

__device__ __forceinline__ float f_lg2(float x) {
    float r; asm("lg2.approx.f32 %0, %1;" : "=f"(r) : "f"(x)); return r;
}
__device__ __forceinline__ float f_ex2(float x) {
    float r; asm("ex2.approx.f32 %0, %1;" : "=f"(r) : "f"(x)); return r;
}
__device__ __forceinline__ float f_sqt(float x) {
    float r; asm("sqrt.approx.f32 %0, %1;" : "=f"(r) : "f"(x)); return r;
}

// Pointwise PCEN. mp = m/S (scaled EMA state). SQ = (1/root == 0.5) fast path.
template <bool SQ>
__device__ __forceinline__ float pcen_pt(float xv, float mp, float na, float d,
                                         float ri, float t3) {
    float mm     = fmaf(S_COEF, mp, FLOORV);       // FLOOR + m  (off-chain)
    float inv_t1 = f_ex2(na * f_lg2(mm));          // (FLOOR+m)^(-alpha)
    float y      = fmaf(xv, inv_t1, d);            // x/term1 + delta
    float t2     = SQ ? f_sqt(y) : f_ex2(ri * f_lg2(y));
    return t2 - t3;
}

template <bool SQ>
__device__ __forceinline__ void run_seq(const float2* __restrict__ px,
                                        float2* __restrict__ po,
                                        int tstart, int t0, int tend,
                                        float2 na, float2 d, float2 ri, float2 t3) {
    float2 x0 = px[0];
    float mx = x0.x * INV_S;            // scaled state m' = m/S; m_init = x_init
    float my = x0.y * INV_S;
    const float2* p = px + STRIDE;

    if (tstart == t0) {                 // chunk 0 emits row 0 (m = x_0, exact)
        float2 o;
        o.x = pcen_pt<SQ>(x0.x, mx, na.x, d.x, ri.x, t3.x);
        o.y = pcen_pt<SQ>(x0.y, my, na.y, d.y, ri.y, t3.y);
        __stcs(po, o);
        po += STRIDE;
    }

    // ---- halo burn-in: EMA update only, batched loads ----
    int nh = t0 - (tstart + 1);         // 320 for chunks > 0, -1 for chunk 0
    int hb = nh / U;                    // 20 full tiles (HALO-1 divisible by U)
    for (int g = 0; g < hb; ++g) {
        float2 xs[U];
        #pragma unroll
        for (int i = 0; i < U; ++i) xs[i] = p[i * STRIDE];
        #pragma unroll
        for (int i = 0; i < U; ++i) {
            mx = fmaf(OMS, mx, xs[i].x);
            my = fmaf(OMS, my, xs[i].y);
        }
        p += U * STRIDE;
    }
    int hr = nh - hb * U;
    for (int i = 0; i < hr; ++i) {
        float2 xv = p[i * STRIDE];
        mx = fmaf(OMS, mx, xv.x);
        my = fmaf(OMS, my, xv.y);
    }
    if (hr > 0) p += hr * STRIDE;

    // ---- emit region ----
    int ne = (tstart == t0) ? (tend - t0 - 1) : (tend - t0);
    int mt = ne / U;
    int rem = ne - mt * U;

    for (int it = 0; it < mt; ++it) {
        float2 xs[U], os[U];
        #pragma unroll
        for (int i = 0; i < U; ++i) xs[i] = p[i * STRIDE];   // batched LDG.64 x16
        #pragma unroll
        for (int i = 0; i < U; ++i) {
            mx = fmaf(OMS, mx, xs[i].x);                     // 4-cyc chain
            my = fmaf(OMS, my, xs[i].y);
            os[i].x = pcen_pt<SQ>(xs[i].x, mx, na.x, d.x, ri.x, t3.x);
            os[i].y = pcen_pt<SQ>(xs[i].y, my, na.y, d.y, ri.y, t3.y);
        }
        #pragma unroll
        for (int i = 0; i < U; ++i) __stcs(po + i * STRIDE, os[i]);
        p  += U * STRIDE;
        po += U * STRIDE;
    }
    for (int i = 0; i < rem; ++i) {
        float2 xv = p[i * STRIDE];
        mx = fmaf(OMS, mx, xv.x);
        my = fmaf(OMS, my, xv.y);
        float2 o;
        o.x = pcen_pt<SQ>(xv.x, mx, na.x, d.x, ri.x, t3.x);
        o.y = pcen_pt<SQ>(xv.y, my, na.y, d.y, ri.y, t3.y);
        __stcs(po + i * STRIDE, o);
    }
}

__global__ void __launch_bounds__(THREADS, 1)
pcen_kernel(const float* __restrict__ x,
            const float* __restrict__ alpha,
            const float* __restrict__ delta,
            const float* __restrict__ root,
            float* __restrict__ out) {
    int gtid = blockIdx.x * blockDim.x + threadIdx.x;
    int w    = gtid >> 5;
    int lane = threadIdx.x & 31;

    // warp -> (b, chunk, half); 16 warps per batch; thread -> 2 channels
    int b     = w >> 4;
    int r     = w & 15;
    int chunk = r >> 1;
    int half  = r & 1;
    int c     = half * 64 + lane * 2;

    // per-channel constants (x2)
    float2 a2 = *(const float2*)(alpha + c);
    float2 d2 = *(const float2*)(delta + c);
    float2 r2 = *(const float2*)(root  + c);

    float2 na, ri, t3;
    na.x = -fminf(a2.x, 1.0f);
    na.y = -fminf(a2.y, 1.0f);
    ri.x = 1.0f / fmaxf(r2.x, 1.0f);
    ri.y = 1.0f / fmaxf(r2.y, 1.0f);
    bool sq = (ri.x == 0.5f) && (ri.y == 0.5f);
    // term3 via the SAME approx path as term2 so the x->0 limit cancels exactly
    t3.x = sq ? f_sqt(d2.x) : f_ex2(ri.x * f_lg2(d2.x));
    t3.y = sq ? f_sqt(d2.y) : f_ex2(ri.y * f_lg2(d2.y));

    int t0     = chunk * CHUNK;
    int tstart = t0 - HALO; if (tstart < 0) tstart = 0;
    int tend   = t0 + CHUNK;

    const float2* px = (const float2*)(x   + ((size_t)b * Tn + tstart) * Cn + c);
    float2*       po = (float2*)      (out + ((size_t)b * Tn + t0)     * Cn + c);

    if (sq) run_seq<true >(px, po, tstart, t0, tend, na, d2, ri, t3);
    else    run_seq<false>(px, po, tstart, t0, tend, na, d2, ri, t3);
}

extern "C" void kernel_launch(void* const* d_in, const int* in_sizes, int n_in,
                              void* d_out, int out_size) {
    const float* x     = (const float*)d_in[0];
    const float* alpha = (const float*)d_in[1];
    const float* delta = (const float*)d_in[2];
    const float* root  = (const float*)d_in[3];
    float*       out   = (float*)d_out;
    (void)in_sizes; (void)n_in; (void)out_size;

    pcen_kernel<<<NBLOCKS, THREADS>>>(x, alpha, delta, root, out);
}